// round 17
// baseline (speedup 1.0000x reference)
#include <cuda_runtime.h>
#include <cuda_bf16.h>
#include <cuda_fp16.h>
#include <math.h>
#include <stdint.h>

// ---------------- scratch (device globals: allocation-free) ----------------
static __device__ __half g_xh[401408];               // x fp16: (512,28,28)
static __device__ __half g_wc1[24576];               // conv1 w fp16 padded: [256][96]
static __device__ __half g_yh[52428800];             // conv1 out fp16 CHANNEL-LAST: (512,20,20,256)
static __device__ signed char g_y8[52428800];        // y quantized int8 (same layout)
static __device__ signed char g_w8[5308416];         // prim_w int8 reordered: [256][(kh*9+kw)*256+ci]
static __device__ float g_wsc[256];                  // per-co weight scale (max/127)
static __device__ int g_ymaxi[512];                  // per-image |y| max (float bits)
static __device__ float g_u[4718592];                // u: (512,1152,8)
static __device__ __half g_priors[94371840];         // priors fp16: (512,10,1152,16)
static __device__ float g_logits[5120];              // (512,10)

// ---------------- helpers ----------------
__device__ __forceinline__ uint32_t smem_u32(const void* p) {
    uint32_t a;
    asm("{ .reg .u64 t; cvta.to.shared.u64 t, %1; cvt.u32.u64 %0, t; }" : "=r"(a) : "l"(p));
    return a;
}
__device__ __forceinline__ void ldsm4(uint32_t* r, uint32_t addr) {
    asm volatile("ldmatrix.sync.aligned.m8n8.x4.shared.b16 {%0,%1,%2,%3}, [%4];"
                 : "=r"(r[0]), "=r"(r[1]), "=r"(r[2]), "=r"(r[3]) : "r"(addr));
}
__device__ __forceinline__ void mma_f16(float* c, const uint32_t* a, uint32_t b0, uint32_t b1) {
    asm volatile("mma.sync.aligned.m16n8k16.row.col.f32.f16.f16.f32 "
                 "{%0,%1,%2,%3}, {%4,%5,%6,%7}, {%8,%9}, {%0,%1,%2,%3};"
                 : "+f"(c[0]), "+f"(c[1]), "+f"(c[2]), "+f"(c[3])
                 : "r"(a[0]), "r"(a[1]), "r"(a[2]), "r"(a[3]), "r"(b0), "r"(b1));
}
__device__ __forceinline__ void mma_s8(int* c, const uint32_t* a, uint32_t b0, uint32_t b1) {
    asm volatile("mma.sync.aligned.m16n8k32.row.col.s32.s8.s8.s32 "
                 "{%0,%1,%2,%3}, {%4,%5,%6,%7}, {%8,%9}, {%0,%1,%2,%3};"
                 : "+r"(c[0]), "+r"(c[1]), "+r"(c[2]), "+r"(c[3])
                 : "r"(a[0]), "r"(a[1]), "r"(a[2]), "r"(a[3]), "r"(b0), "r"(b1));
}
__device__ __forceinline__ void cp_async16(uint32_t saddr, const void* gaddr) {
    asm volatile("cp.async.cg.shared.global [%0], [%1], 16;" :: "r"(saddr), "l"(gaddr));
}
__device__ __forceinline__ void cp_commit() { asm volatile("cp.async.commit_group;"); }
__device__ __forceinline__ void cp_wait0() { asm volatile("cp.async.wait_group 0;" ::: "memory"); }

// ---------------- prep: x -> fp16, conv1 w -> fp16 padded, reset ymax ----------------
__global__ void __launch_bounds__(256) prep_kernel(const float* __restrict__ x,
                                                   const float* __restrict__ cw) {
    int i = blockIdx.x * 256 + threadIdx.x;
    if (i < 401408) g_xh[i] = __float2half(x[i]);
    if (i < 24576) {
        int co = i / 96, k = i - co * 96;
        g_wc1[i] = (k < 81) ? __float2half(cw[co * 81 + k]) : __half(0.f);
    }
    if (i < 512) g_ymaxi[i] = 0;
}

// ---------------- conv1 via warp-MMA fp16 implicit GEMM (+ per-image absmax) ----------------
#define C1_STRIDE 208
#define C1_A 1024
#define C1_B 27648
__global__ void __launch_bounds__(256, 2) conv1_mma_kernel(const float* __restrict__ cb) {
    extern __shared__ char smc[];
    int* s_nbase = (int*)smc;
    float* s_bias = (float*)(smc + 512);
    uint32_t sb = smem_u32(smc);

    int tid = threadIdx.x, lane = tid & 31, wid = tid >> 5;
    int co0 = blockIdx.x * 128;
    int n0 = blockIdx.y * 128;

    if (tid < 128) {
        int n = n0 + tid;
        int b = n / 400, pos = n - b * 400;
        int oh = pos / 20, ow = pos - oh * 20;
        s_nbase[tid] = b * 784 + oh * 28 + ow;
        s_bias[tid] = cb[co0 + tid];
    }

    {
        int row = tid >> 1;
        int cbase = (tid & 1) * 6;
#pragma unroll
        for (int q = 0; q < 6; q++) {
            int ch = cbase + q;
            cp_async16(sb + C1_B + (uint32_t)row * C1_STRIDE + (uint32_t)ch * 16,
                       g_wc1 + (size_t)(co0 + row) * 96 + ch * 8);
        }
        cp_commit();
    }
    __syncthreads();

    {
        int row = tid >> 1, h = tid & 1;
        int base = s_nbase[row];
        __half* arow = (__half*)(smc + C1_A + (size_t)row * C1_STRIDE);
        int kh0 = h ? 5 : 0, kh1 = h ? 9 : 5;
        for (int kh = kh0; kh < kh1; kh++) {
            const __half* src = g_xh + base + kh * 28;
#pragma unroll
            for (int kw = 0; kw < 9; kw++) arow[kh * 9 + kw] = src[kw];
        }
        if (h) {
#pragma unroll
            for (int k = 81; k < 96; k++) arow[k] = __half(0.f);
        }
    }
    cp_wait0();
    __syncthreads();

    int warp_m = wid >> 1, warp_n = wid & 1;
    uint32_t a_off = C1_A + (uint32_t)(warp_m * 32 + (lane & 7) + ((lane >> 3) & 1) * 8) * C1_STRIDE
                     + (uint32_t)(lane >> 4) * 16;
    uint32_t b_off = C1_B + (uint32_t)(warp_n * 64 + (lane & 7) + ((lane >> 4) & 1) * 8) * C1_STRIDE
                     + (uint32_t)((lane >> 3) & 1) * 16;

    float acc[2][8][4];
#pragma unroll
    for (int m = 0; m < 2; m++)
#pragma unroll
        for (int nf = 0; nf < 8; nf++)
#pragma unroll
            for (int e = 0; e < 4; e++) acc[m][nf][e] = 0.f;

#pragma unroll
    for (int ks = 0; ks < 6; ks++) {
        uint32_t ko = (uint32_t)ks * 32;
        uint32_t a0[4], a1[4];
        ldsm4(a0, sb + a_off + ko);
        ldsm4(a1, sb + a_off + 16 * C1_STRIDE + ko);
#pragma unroll
        for (int jj = 0; jj < 4; jj++) {
            uint32_t bb[4];
            ldsm4(bb, sb + b_off + (uint32_t)jj * (16 * C1_STRIDE) + ko);
            mma_f16(acc[0][2 * jj],     a0, bb[0], bb[1]);
            mma_f16(acc[1][2 * jj],     a1, bb[0], bb[1]);
            mma_f16(acc[0][2 * jj + 1], a0, bb[2], bb[3]);
            mma_f16(acc[1][2 * jj + 1], a1, bb[2], bb[3]);
        }
    }

    int row0 = warp_m * 32 + (lane >> 2);
#pragma unroll
    for (int m = 0; m < 2; m++) {
        int n_a = n0 + row0 + m * 16;
        int n_b = n_a + 8;
        float mxa = 0.f, mxb = 0.f;
#pragma unroll
        for (int nf = 0; nf < 8; nf++) {
            int col = warp_n * 64 + nf * 8 + (lane & 3) * 2;
            float b0 = s_bias[col], b1 = s_bias[col + 1];
            float v0 = acc[m][nf][0] + b0, v1 = acc[m][nf][1] + b1;
            float v2 = acc[m][nf][2] + b0, v3 = acc[m][nf][3] + b1;
            mxa = fmaxf(mxa, fmaxf(fabsf(v0), fabsf(v1)));
            mxb = fmaxf(mxb, fmaxf(fabsf(v2), fabsf(v3)));
            *(__half2*)(g_yh + (size_t)n_a * 256 + co0 + col) = __floats2half2_rn(v0, v1);
            *(__half2*)(g_yh + (size_t)n_b * 256 + co0 + col) = __floats2half2_rn(v2, v3);
        }
        atomicMax(&g_ymaxi[n_a / 400], __float_as_int(mxa));
        atomicMax(&g_ymaxi[n_b / 400], __float_as_int(mxb));
    }
}

// ---------------- quantize y: fp16 -> int8 per-image scale ----------------
__device__ __forceinline__ uint32_t q4(float a, float b, float c, float d, float r) {
    int qa = max(-127, min(127, __float2int_rn(a * r)));
    int qb = max(-127, min(127, __float2int_rn(b * r)));
    int qc = max(-127, min(127, __float2int_rn(c * r)));
    int qd = max(-127, min(127, __float2int_rn(d * r)));
    return (uint32_t)(qa & 0xFF) | ((uint32_t)(qb & 0xFF) << 8) |
           ((uint32_t)(qc & 0xFF) << 16) | ((uint32_t)(qd & 0xFF) << 24);
}
__global__ void __launch_bounds__(256) quanty_kernel() {
    int b = blockIdx.x, tid = threadIdx.x;
    float r = 127.f / __int_as_float(g_ymaxi[b]);
    const uint4* src = (const uint4*)(g_yh + (size_t)b * 102400);
    uint2* dst = (uint2*)(g_y8 + (size_t)b * 102400);
    for (int i = tid; i < 12800; i += 256) {
        uint4 v = src[i];
        float2 f0 = __half22float2(*(__half2*)&v.x);
        float2 f1 = __half22float2(*(__half2*)&v.y);
        float2 f2 = __half22float2(*(__half2*)&v.z);
        float2 f3 = __half22float2(*(__half2*)&v.w);
        dst[i] = make_uint2(q4(f0.x, f0.y, f1.x, f1.y, r), q4(f2.x, f2.y, f3.x, f3.y, r));
    }
}

// ---------------- prim_w -> int8 + per-co scale, reorder k: (ci,kh,kw) -> (kh*9+kw)*256+ci ----------------
__global__ void __launch_bounds__(256) wconv_kernel(const float* __restrict__ w) {
    __shared__ __half sw[81 * 258];
    __shared__ float wred[8];
    int co = blockIdx.x, tid = threadIdx.x;
    const float* src = w + (size_t)co * 20736;
    float mx = 0.f;
    for (int i = tid; i < 20736; i += 256) {
        float v = src[i];
        mx = fmaxf(mx, fabsf(v));
        int ci = i / 81, rr = i - ci * 81;
        sw[rr * 258 + ci] = __float2half(v);
    }
#pragma unroll
    for (int s = 16; s; s >>= 1) mx = fmaxf(mx, __shfl_xor_sync(0xffffffffu, mx, s));
    if ((tid & 31) == 0) wred[tid >> 5] = mx;
    __syncthreads();
    if (tid == 0) {
        float m = wred[0];
#pragma unroll
        for (int i = 1; i < 8; i++) m = fmaxf(m, wred[i]);
        wred[0] = m;
        g_wsc[co] = m * (1.f / 127.f);
    }
    __syncthreads();
    float r = 127.f / wred[0];
    signed char* dst = g_w8 + (size_t)co * 20736;
    for (int t = tid; t < 20736; t += 256) {
        int rr = t >> 8, ci = t & 255;
        int q = __float2int_rn(__half2float(sw[rr * 258 + ci]) * r);
        dst[t] = (signed char)max(-127, min(127, q));
    }
}

// ---------------- conv2 via warp-MMA int8 IMMA implicit GEMM ----------------
// C[n,co] = sum_k qy[n,k] * qw[co,k]; BK=128 int8 (162 iters), dequant in epilogue.
// Stage: A rows 0-127 (128B payload), B rows 128-255; stride 144 -> 36864B; 2 stages, 2 CTAs/SM.
#define A_STRIDE 144
#define STAGE_BYTES 36864
__global__ void __launch_bounds__(256, 2) conv2_mma_kernel(const float* __restrict__ pb) {
    extern __shared__ char smc[];
    int* s_nbase = (int*)smc;                 // [128]
    float* s_bias = (float*)(smc + 512);      // [128]
    float* s_wsc = (float*)(smc + 1024);      // [128]
    int* s_koff = (int*)(smc + 1536);         // [162]
    uint32_t sT = smem_u32(smc + 2304);

    int tid = threadIdx.x, lane = tid & 31, wid = tid >> 5;
    int co0 = blockIdx.x * 128;
    int n0 = blockIdx.y * 128;

    if (tid < 128) {
        int n = n0 + tid;
        int b = n / 36, pos = n - b * 36;
        int oh = pos / 6, ow = pos - oh * 6;
        s_nbase[tid] = ((b * 20 + 2 * oh) * 20 + 2 * ow) * 256;
        s_bias[tid] = pb[co0 + tid];
        s_wsc[tid] = g_wsc[co0 + tid];
    }
    if (tid < 162) {
        int khw = tid >> 1;
        int kh = khw / 9, kw = khw - 9 * kh;
        s_koff[tid] = (kh * 20 + kw) * 256 + (tid & 1) * 128;
    }
    __syncthreads();

    int j = tid & 7;
    int rowq = tid >> 3;

    int warp_m = wid >> 1, warp_n = wid & 1;
    uint32_t a_off = (uint32_t)(warp_m * 32 + (lane & 7) + ((lane >> 3) & 1) * 8) * A_STRIDE
                     + (uint32_t)(lane >> 4) * 16;
    uint32_t b_off = 128u * A_STRIDE + (uint32_t)(warp_n * 64 + (lane & 7) + ((lane >> 4) & 1) * 8) * A_STRIDE
                     + (uint32_t)((lane >> 3) & 1) * 16;

    int acc[2][8][4];
#pragma unroll
    for (int m = 0; m < 2; m++)
#pragma unroll
        for (int nf = 0; nf < 8; nf++)
#pragma unroll
            for (int e = 0; e < 4; e++) acc[m][nf][e] = 0;

#define PRODUCE(sidx, cidx)                                                            \
    do {                                                                               \
        uint32_t st_ = sT + (uint32_t)(sidx) * STAGE_BYTES;                            \
        int koff_ = s_koff[(cidx)];                                                    \
        int k0_ = (cidx) * 128;                                                        \
        _Pragma("unroll")                                                              \
        for (int rr = 0; rr < 4; rr++) {                                               \
            int row = rowq + rr * 32;                                                  \
            const signed char* ga = g_y8 + s_nbase[row] + koff_ + j * 16;              \
            cp_async16(st_ + (uint32_t)row * A_STRIDE + (uint32_t)j * 16, ga);         \
            const signed char* gb = g_w8 + (size_t)(co0 + row) * 20736 + k0_ + j * 16; \
            cp_async16(st_ + (uint32_t)(128 + row) * A_STRIDE + (uint32_t)j * 16, gb); \
        }                                                                              \
        cp_commit();                                                                   \
    } while (0)

    PRODUCE(0, 0);

    for (int c = 0; c < 162; c++) {
        uint32_t stage = sT + (uint32_t)(c & 1) * STAGE_BYTES;
        cp_wait0();
        __syncthreads();
        if (c + 1 < 162) PRODUCE((c + 1) & 1, c + 1);

#pragma unroll
        for (int ks = 0; ks < 4; ks++) {
            uint32_t ko = (uint32_t)ks * 32;
            uint32_t a0[4], a1[4];
            ldsm4(a0, stage + a_off + ko);
            ldsm4(a1, stage + a_off + 16 * A_STRIDE + ko);
#pragma unroll
            for (int jj = 0; jj < 4; jj++) {
                uint32_t bb[4];
                ldsm4(bb, stage + b_off + (uint32_t)jj * (16 * A_STRIDE) + ko);
                mma_s8(acc[0][2 * jj],     a0, bb[0], bb[1]);
                mma_s8(acc[1][2 * jj],     a1, bb[0], bb[1]);
                mma_s8(acc[0][2 * jj + 1], a0, bb[2], bb[3]);
                mma_s8(acc[1][2 * jj + 1], a1, bb[2], bb[3]);
            }
        }
    }

    // epilogue: dequant + bias, write raw p into u layout
    int row0 = warp_m * 32 + (lane >> 2);
#pragma unroll
    for (int m = 0; m < 2; m++) {
        int r_a = row0 + m * 16;
        int n_a = n0 + r_a, n_b = n_a + 8;
        int ba = n_a / 36, pa = n_a - ba * 36;
        int bb2 = n_b / 36, pbs = n_b - bb2 * 36;
        float sya = __int_as_float(g_ymaxi[ba]) * (1.f / 127.f);
        float syb = __int_as_float(g_ymaxi[bb2]) * (1.f / 127.f);
        size_t ua = (size_t)ba * 9216 + (size_t)pa * 8;
        size_t ub = (size_t)bb2 * 9216 + (size_t)pbs * 8;
#pragma unroll
        for (int nf = 0; nf < 8; nf++) {
            int col = warp_n * 64 + nf * 8 + (lane & 3) * 2;
#pragma unroll
            for (int e = 0; e < 2; e++) {
                int lc = col + e;
                int co = co0 + lc;
                float sw = s_wsc[lc], bias = s_bias[lc];
                size_t roff = (size_t)((co & 31) * 36) * 8 + (co >> 5);
                g_u[ua + roff] = (float)acc[m][nf][e] * (sya * sw) + bias;
                g_u[ub + roff] = (float)acc[m][nf][2 + e] * (syb * sw) + bias;
            }
        }
    }
}

// ---------------- squash u in place ----------------
__global__ void squash_kernel() {
    int idx = blockIdx.x * 256 + threadIdx.x;
    if (idx >= 512 * 1152) return;
    float4 v0 = *reinterpret_cast<float4*>(&g_u[(size_t)idx * 8]);
    float4 v1 = *reinterpret_cast<float4*>(&g_u[(size_t)idx * 8 + 4]);
    float sn = v0.x * v0.x + v0.y * v0.y + v0.z * v0.z + v0.w * v0.w +
               v1.x * v1.x + v1.y * v1.y + v1.z * v1.z + v1.w * v1.w;
    float sc = sqrtf(sn) / (1.f + sn);
    v0.x *= sc; v0.y *= sc; v0.z *= sc; v0.w *= sc;
    v1.x *= sc; v1.y *= sc; v1.z *= sc; v1.w *= sc;
    *reinterpret_cast<float4*>(&g_u[(size_t)idx * 8]) = v0;
    *reinterpret_cast<float4*>(&g_u[(size_t)idx * 8 + 4]) = v1;
}

// ---------------- priors: 4 outputs per u load; b split over threads+grid.z ----------------
__global__ void __launch_bounds__(256) priors_kernel(const float* __restrict__ rw) {
    int tid = threadIdx.x;
    int r0 = blockIdx.x * 16;
    int c0 = blockIdx.y * 2;
    int b0 = blockIdx.z * 128;
    int bh = tid >> 7, rl = (tid >> 3) & 15, op = tid & 7;

    float wr[2][2][8];
#pragma unroll
    for (int c2 = 0; c2 < 2; c2++)
#pragma unroll
        for (int o2 = 0; o2 < 2; o2++)
#pragma unroll
            for (int i = 0; i < 8; i++)
                wr[c2][o2][i] = rw[(size_t)(c0 + c2) * 147456 + (size_t)(r0 + rl) * 128 + i * 16 + op * 2 + o2];

    const float4* usrc = (const float4*)(g_u + (size_t)(r0 + rl) * 8);
    size_t poff = (size_t)(r0 + rl) * 16 + op * 2;

    for (int b = b0 + bh; b < b0 + 128; b += 2) {
        float4 u0 = __ldg(usrc + (size_t)b * 2304);
        float4 u1 = __ldg(usrc + (size_t)b * 2304 + 1);
#pragma unroll
        for (int c2 = 0; c2 < 2; c2++) {
            float a0 = u0.x * wr[c2][0][0] + u0.y * wr[c2][0][1] + u0.z * wr[c2][0][2] + u0.w * wr[c2][0][3] +
                       u1.x * wr[c2][0][4] + u1.y * wr[c2][0][5] + u1.z * wr[c2][0][6] + u1.w * wr[c2][0][7];
            float a1 = u0.x * wr[c2][1][0] + u0.y * wr[c2][1][1] + u0.z * wr[c2][1][2] + u0.w * wr[c2][1][3] +
                       u1.x * wr[c2][1][4] + u1.y * wr[c2][1][5] + u1.z * wr[c2][1][6] + u1.w * wr[c2][1][7];
            __half2 h = __floats2half2_rn(a0, a1);
            *(__half2*)(g_priors + (size_t)(b * 10 + c0 + c2) * 18432 + poff) = h;
        }
    }
}

// ---------------- routing: it0 uniform fast path; exp without max-sub ----------------
__device__ __forceinline__ float blk_reduce_sum(float v, float* red) {
#pragma unroll
    for (int s = 16; s; s >>= 1) v += __shfl_xor_sync(0xffffffffu, v, s);
    if ((threadIdx.x & 31) == 0) red[threadIdx.x >> 5] = v;
    __syncthreads();
    float r = red[0];
#pragma unroll
    for (int i = 1; i < 8; i++) r += red[i];
    __syncthreads();
    return r;
}

__global__ void __launch_bounds__(256) routing_kernel() {
    extern __shared__ float sm[];
    uint32_t* P2   = (uint32_t*)sm;            // [1152*9] half2 words (pad stride 9)
    float* blog    = sm + 10368;
    float* probs   = sm + 11520;
    float2* sred   = (float2*)(sm + 12672);
    float* s_s     = sm + 13184;
    float2* v2     = (float2*)(sm + 13200);
    float* red     = sm + 13216;

    int tid = threadIdx.x;
    int b = blockIdx.x, c = blockIdx.y;
    const uint4* gp = (const uint4*)(g_priors + ((size_t)b * 10 + c) * 18432);
    for (int i = tid; i < 2304; i += 256) {
        uint4 v = __ldg(gp + i);
        int r = i >> 1, part = (i & 1) * 4;
        uint32_t* dst = &P2[r * 9 + part];
        dst[0] = v.x; dst[1] = v.y; dst[2] = v.z; dst[3] = v.w;
    }
    __syncthreads();

    int o2 = tid & 7, rg = tid >> 3;
    for (int it = 0; it < 3; it++) {
        float inv;
        if (it == 0) {
            inv = 1.f / 1152.f;            // softmax of zeros is uniform
        } else {
            float se = 0.f;
            for (int r = tid; r < 1152; r += 256) {
                float e = expf(blog[r]);   // |blog| small; no max-sub needed
                probs[r] = e;
                se += e;
            }
            se = blk_reduce_sum(se, red);
            inv = 1.f / se;
        }

        float2 acc = make_float2(0.f, 0.f);
        if (it == 0) {
            for (int r = rg; r < 1152; r += 32) {
                float2 f = __half22float2(*(__half2*)&P2[r * 9 + o2]);
                acc.x += f.x;
                acc.y += f.y;
            }
        } else {
            for (int r = rg; r < 1152; r += 32) {
                float2 f = __half22float2(*(__half2*)&P2[r * 9 + o2]);
                float p = probs[r];
                acc.x = fmaf(p, f.x, acc.x);
                acc.y = fmaf(p, f.y, acc.y);
            }
        }
        sred[tid] = acc;
        __syncthreads();
        if (tid < 16) {
            int oo2 = tid >> 1, comp = tid & 1;
            float s = 0.f;
#pragma unroll
            for (int g = 0; g < 32; g++) {
                float2 t = sred[g * 8 + oo2];
                s += comp ? t.y : t.x;
            }
            s_s[tid] = s * inv;
        }
        __syncthreads();
        if (tid < 8) {
            float sn = 0.f;
#pragma unroll
            for (int oo = 0; oo < 16; oo++) sn += s_s[oo] * s_s[oo];
            float sc = sqrtf(sn) / (1.f + sn);
            v2[tid] = make_float2(s_s[2 * tid] * sc, s_s[2 * tid + 1] * sc);
            if (tid == 0 && it == 2) g_logits[b * 10 + c] = sn / (1.f + sn);
        }
        __syncthreads();
        if (it < 2) {
            for (int r = tid; r < 1152; r += 256) {
                float a = 0.f;
#pragma unroll
                for (int jj = 0; jj < 8; jj++) {
                    float2 f = __half22float2(*(__half2*)&P2[r * 9 + jj]);
                    float2 vv = v2[jj];
                    a = fmaf(f.x, vv.x, a);
                    a = fmaf(f.y, vv.y, a);
                }
                blog[r] = (it == 0) ? a : blog[r] + a;
            }
            __syncthreads();
        }
    }
}

// ---------------- final softmax over 10 classes ----------------
__global__ void final_kernel(float* __restrict__ out) {
    int b = blockIdx.x * blockDim.x + threadIdx.x;
    if (b >= 512) return;
    float l[10];
    float mx = -1e30f;
#pragma unroll
    for (int i = 0; i < 10; i++) { l[i] = g_logits[b * 10 + i]; mx = fmaxf(mx, l[i]); }
    float se = 0.f;
#pragma unroll
    for (int i = 0; i < 10; i++) { l[i] = expf(l[i] - mx); se += l[i]; }
    float inv = 1.f / se;
#pragma unroll
    for (int i = 0; i < 10; i++) out[b * 10 + i] = l[i] * inv;
}

// ---------------- launch ----------------
extern "C" void kernel_launch(void* const* d_in, const int* in_sizes, int n_in,
                              void* d_out, int out_size) {
    const float* x       = (const float*)d_in[0];
    const float* conv_w  = (const float*)d_in[1];
    const float* conv_b  = (const float*)d_in[2];
    const float* prim_w  = (const float*)d_in[3];
    const float* prim_b  = (const float*)d_in[4];
    const float* route_w = (const float*)d_in[5];
    float* out = (float*)d_out;

    prep_kernel<<<1568, 256>>>(x, conv_w);
    wconv_kernel<<<256, 256>>>(prim_w);
    cudaFuncSetAttribute(conv1_mma_kernel, cudaFuncAttributeMaxDynamicSharedMemorySize, 54528);
    conv1_mma_kernel<<<dim3(2, 1600), 256, 54528>>>(conv_b);
    quanty_kernel<<<512, 256>>>();
    cudaFuncSetAttribute(conv2_mma_kernel, cudaFuncAttributeMaxDynamicSharedMemorySize, 76032);
    conv2_mma_kernel<<<dim3(2, 144), 256, 76032>>>(prim_b);
    squash_kernel<<<2304, 256>>>();
    priors_kernel<<<dim3(72, 5, 4), 256>>>(route_w);
    cudaFuncSetAttribute(routing_kernel, cudaFuncAttributeMaxDynamicSharedMemorySize, 52896);
    routing_kernel<<<dim3(512, 10), 256, 52896>>>();
    final_kernel<<<2, 256>>>(out);
}